// round 1
// baseline (speedup 1.0000x reference)
#include <cuda_runtime.h>
#include <stdint.h>

// Problem constants (fixed by setup_inputs)
#define En   256      // embedding E
#define Kk   8        // K
#define Bn   8        // batch
#define Tcn  1024     // Tc
#define T1n  8192     // Tc*K
#define TTn  24576    // T1 + TLAST (value row length)
#define Mm   2048     // num_mix
#define V1   17       // V+1
#define JV   136      // K * V1

// Scratch (static device memory; no allocations allowed)
__device__ float g_Wf[En * JV];          // Wf[e][j*17+v] = sum_o W0[e,o,j]*Wl[v,o]
__device__ float g_G[Kk * En * JV];      // G[jm][f][jv]  = sum_e W1[f,e,jm]*Wf[e,jv]
__device__ float g_dvec[JV];             // d[jv] = sum_e b1[e]*Wf[e,jv] + sum_o b0[o]*Wl[v,o] + bl[v]
__device__ int   g_bucket[Bn][Kk][Mm];   // packed (t<<11)|m per (b, jm)
__device__ int   g_cnt[Bn][Kk];

// ---------------------------------------------------------------------------
// Kernel 1: stable compaction of value==2 positions, bucketed by jm = pos & 7.
// One block per batch, 1024 threads, 8 contiguous elements each (stable rank).
// Handles value stored as int32 or int64 (detected from high word of elem 0;
// all value entries are >= 1, so the probe is unambiguous).
// ---------------------------------------------------------------------------
__global__ void compact_kernel(const unsigned int* __restrict__ v32) {
    int b   = blockIdx.x;
    int tid = threadIdx.x;
    __shared__ int wsum[32];

    if (tid < Kk) g_cnt[b][tid] = 0;

    bool is64 = (v32[1] == 0u);

    int vals[8];
    int c = 0;
    int i0 = tid * 8;
#pragma unroll
    for (int q = 0; q < 8; q++) {
        int i = i0 + q;
        int idx = b * TTn + i;
        int val = is64 ? (int)v32[2 * idx] : (int)v32[idx];
        vals[q] = val;
        c += (val == 2);
    }

    // block-wide exclusive scan of per-thread counts
    int lane = tid & 31, w = tid >> 5;
    int x = c;
#pragma unroll
    for (int d = 1; d < 32; d <<= 1) {
        int y = __shfl_up_sync(0xffffffffu, x, d);
        if (lane >= d) x += y;
    }
    if (lane == 31) wsum[w] = x;
    __syncthreads();
    if (w == 0) {
        int s = wsum[lane];
#pragma unroll
        for (int d = 1; d < 32; d <<= 1) {
            int y = __shfl_up_sync(0xffffffffu, s, d);
            if (lane >= d) s += y;
        }
        wsum[lane] = s;
    }
    __syncthreads();
    int m = x - c + (w > 0 ? wsum[w - 1] : 0);  // rank of first hit in my range

#pragma unroll
    for (int q = 0; q < 8; q++) {
        if (vals[q] == 2) {
            int i  = i0 + q;
            int jm = i & 7;
            int t  = i >> 3;
            int slot = atomicAdd(&g_cnt[b][jm], 1);
            g_bucket[b][jm][slot] = (t << 11) | m;
            m++;
        }
    }
}

// ---------------------------------------------------------------------------
// Kernel 2: Wf[e][jv] = sum_o W0[e,o,j] * Wl[v,o]   (one block per e)
// ---------------------------------------------------------------------------
__global__ void wf_kernel(const float* __restrict__ W0, const float* __restrict__ Wl) {
    int e = blockIdx.x;
    __shared__ float w0r[En * Kk];   // 2048
    __shared__ float wls[V1 * En];   // 4352
    for (int idx = threadIdx.x; idx < En * Kk; idx += blockDim.x)
        w0r[idx] = W0[e * En * Kk + idx];
    for (int idx = threadIdx.x; idx < V1 * En; idx += blockDim.x)
        wls[idx] = Wl[idx];
    __syncthreads();
    int jv = threadIdx.x;
    if (jv < JV) {
        int j = jv / V1, v = jv % V1;
        float s = 0.f;
#pragma unroll 8
        for (int o = 0; o < En; o++)
            s += w0r[o * Kk + j] * wls[v * En + o];
        g_Wf[e * JV + jv] = s;
    }
}

// ---------------------------------------------------------------------------
// Kernel 3: d[jv] = sum_e b1[e]*Wf[e,jv] + sum_o b0[o]*Wl[v,o] + bl[v]
// ---------------------------------------------------------------------------
__global__ void d_kernel(const float* __restrict__ b1, const float* __restrict__ b0,
                         const float* __restrict__ Wl, const float* __restrict__ bl) {
    int jv = threadIdx.x;
    if (jv >= JV) return;
    int v = jv % V1;
    float s = 0.f;
    for (int e = 0; e < En; e++) s += b1[e] * g_Wf[e * JV + jv];
    float cc = 0.f;
    for (int o = 0; o < En; o++) cc += b0[o] * Wl[v * En + o];
    g_dvec[jv] = s + cc + bl[v];
}

// ---------------------------------------------------------------------------
// Kernel 4: G[jm][f][jv] = sum_e W1[f,e,jm] * Wf[e,jv]
// grid (8 f-tiles of 32, 8 jm), 128 threads: 16 f-pairs x 8 column groups.
// ---------------------------------------------------------------------------
__global__ void g_kernel(const float* __restrict__ W1) {
    int jm = blockIdx.y;
    int f0 = blockIdx.x * 32;
    int tid = threadIdx.x;
    int fty = tid >> 3;   // 0..15
    int tx  = tid & 7;

    __shared__ float As[32][33];
    __shared__ float Wfs[32 * JV];

    float acc[2][V1];
#pragma unroll
    for (int j = 0; j < 2; j++)
#pragma unroll
        for (int i = 0; i < V1; i++) acc[j][i] = 0.f;

    for (int kc = 0; kc < En; kc += 32) {
        for (int idx = tid; idx < 32 * 32; idx += 128) {
            int fr = idx >> 5, oo = idx & 31;
            As[fr][oo] = W1[(f0 + fr) * (En * Kk) + (kc + oo) * Kk + jm];
        }
        for (int idx = tid; idx < 32 * JV; idx += 128)
            Wfs[idx] = g_Wf[kc * JV + idx];
        __syncthreads();
#pragma unroll
        for (int oo = 0; oo < 32; oo++) {
            float a0 = As[fty * 2 + 0][oo];
            float a1 = As[fty * 2 + 1][oo];
#pragma unroll
            for (int i = 0; i < V1; i++) {
                float g = Wfs[oo * JV + tx + 8 * i];
                acc[0][i] += a0 * g;
                acc[1][i] += a1 * g;
            }
        }
        __syncthreads();
    }
#pragma unroll
    for (int j = 0; j < 2; j++) {
        int f = f0 + fty * 2 + j;
#pragma unroll
        for (int i = 0; i < V1; i++)
            g_G[(jm * En + f) * JV + tx + 8 * i] = acc[j][i];
    }
}

// ---------------------------------------------------------------------------
// Kernel 5: main gather-GEMM.
// out[(b*2048+m)*136 + jv] = sum_f x[b, t_m, f] * G[jm][f][jv] + d[jv]
// grid (16 row-tiles, 8 jm, 8 b); 256 threads: 32 row-threads (TM=4) x 8 col
// groups (TN=17, columns tx + 8*i).
// ---------------------------------------------------------------------------
__global__ __launch_bounds__(256) void main_kernel(const float* __restrict__ x,
                                                   float* __restrict__ out) {
    int b  = blockIdx.z;
    int jm = blockIdx.y;
    int count = g_cnt[b][jm];
    int r0 = blockIdx.x * 128;
    if (r0 >= count) return;

    int tid = threadIdx.x;
    int ty = tid >> 3;   // 0..31
    int tx = tid & 7;

    __shared__ int   Es[128];
    __shared__ float Xs[32][129];
    __shared__ float Gs[32 * JV];

    if (tid < 128) {
        int r = r0 + tid;
        Es[tid] = (r < count) ? g_bucket[b][jm][r] : 0;
    }
    __syncthreads();

    float acc[4][V1];
#pragma unroll
    for (int j = 0; j < 4; j++)
#pragma unroll
        for (int i = 0; i < V1; i++) acc[j][i] = 0.f;

    const float* xb = x + (size_t)b * Tcn * En;
    const float* Gj = g_G + jm * En * JV;

    for (int kc = 0; kc < En; kc += 32) {
#pragma unroll
        for (int idx = tid; idx < 128 * 32; idx += 256) {
            int r = idx >> 5, k = idx & 31;
            int t = Es[r] >> 11;
            Xs[k][r] = xb[t * En + kc + k];
        }
        for (int idx = tid; idx < 32 * JV; idx += 256)
            Gs[idx] = Gj[kc * JV + idx];
        __syncthreads();
#pragma unroll
        for (int kk = 0; kk < 32; kk++) {
            float a0 = Xs[kk][ty * 4 + 0];
            float a1 = Xs[kk][ty * 4 + 1];
            float a2 = Xs[kk][ty * 4 + 2];
            float a3 = Xs[kk][ty * 4 + 3];
#pragma unroll
            for (int i = 0; i < V1; i++) {
                float g = Gs[kk * JV + tx + 8 * i];
                acc[0][i] += a0 * g;
                acc[1][i] += a1 * g;
                acc[2][i] += a2 * g;
                acc[3][i] += a3 * g;
            }
        }
        __syncthreads();
    }

    float dv[V1];
#pragma unroll
    for (int i = 0; i < V1; i++) dv[i] = g_dvec[tx + 8 * i];

#pragma unroll
    for (int j = 0; j < 4; j++) {
        int r = ty * 4 + j;
        if (r0 + r < count) {
            int m = Es[r] & 0x7FF;
            float* op = out + (size_t)(b * Mm + m) * JV;
#pragma unroll
            for (int i = 0; i < V1; i++)
                op[tx + 8 * i] = acc[j][i] + dv[i];
        }
    }
}

// ---------------------------------------------------------------------------
extern "C" void kernel_launch(void* const* d_in, const int* in_sizes, int n_in,
                              void* d_out, int out_size) {
    const float*        x     = (const float*)d_in[0];
    const unsigned int* value = (const unsigned int*)d_in[1];

    // Locate the weight block: W1 is the first input at/after index 4 with
    // E*E*K = 524288 elements (robust to whether num_mix is passed).
    int wi = 4;
    while (wi < n_in && in_sizes[wi] != En * En * Kk) wi++;
    const float* W1 = (const float*)d_in[wi + 0];
    const float* b1 = (const float*)d_in[wi + 1];
    const float* W0 = (const float*)d_in[wi + 2];
    const float* b0 = (const float*)d_in[wi + 3];
    const float* Wl = (const float*)d_in[wi + 4];
    const float* bl = (const float*)d_in[wi + 5];
    float* out = (float*)d_out;

    compact_kernel<<<Bn, 1024>>>(value);
    wf_kernel<<<En, 160>>>(W0, Wl);
    d_kernel<<<1, 160>>>(b1, b0, Wl, bl);
    g_kernel<<<dim3(8, 8), 128>>>(W1);
    main_kernel<<<dim3(16, 8, 8), 256>>>(x, out);
}